// round 13
// baseline (speedup 1.0000x reference)
#include <cuda_runtime.h>
#include <cstdint>

#define D_MODEL 1024
#define N_HEAD 16
#define HEAD_DIM 64
#define B_SZ 4
#define TQ 2048
#define TK 8192
#define STRIDE 16
#define L_CTX 512

__device__ float g_Qh[(size_t)B_SZ * N_HEAD * TQ * HEAD_DIM];
__device__ float g_Kh[(size_t)B_SZ * N_HEAD * L_CTX * HEAD_DIM];
__device__ float g_Vh[(size_t)B_SZ * N_HEAD * L_CTX * HEAD_DIM];
__device__ float g_ctx[(size_t)B_SZ * TQ * D_MODEL];
__device__ float g_qr[(size_t)B_SZ * TQ * D_MODEL];
__device__ float g_rw[(size_t)2 * D_MODEL * D_MODEL];

// ---------------------------------------------------------------------------
__device__ __forceinline__ float tf32_round(float x) {
    uint32_t u;
    asm("cvt.rna.tf32.f32 %0, %1;" : "=r"(u) : "f"(x));
    return __uint_as_float(u);
}
__device__ __forceinline__ uint32_t pack_bf16x2(float lo, float hi) {
    uint32_t r;
    asm("cvt.rn.bf16x2.f32 %0, %1, %2;" : "=r"(r) : "f"(hi), "f"(lo));
    return r;
}
__device__ __forceinline__ void mma_tf32(float* c, const uint32_t* a,
                                         uint32_t b0, uint32_t b1) {
    asm volatile(
        "mma.sync.aligned.m16n8k8.row.col.f32.tf32.tf32.f32 "
        "{%0,%1,%2,%3}, {%4,%5,%6,%7}, {%8,%9}, {%0,%1,%2,%3};\n"
        : "+f"(c[0]), "+f"(c[1]), "+f"(c[2]), "+f"(c[3])
        : "r"(a[0]), "r"(a[1]), "r"(a[2]), "r"(a[3]), "r"(b0), "r"(b1));
}
__device__ __forceinline__ void mma_bf16(float* c, const uint32_t* a,
                                         uint32_t b0, uint32_t b1) {
    asm volatile(
        "mma.sync.aligned.m16n8k16.row.col.f32.bf16.bf16.f32 "
        "{%0,%1,%2,%3}, {%4,%5,%6,%7}, {%8,%9}, {%0,%1,%2,%3};\n"
        : "+f"(c[0]), "+f"(c[1]), "+f"(c[2]), "+f"(c[3])
        : "r"(a[0]), "r"(a[1]), "r"(a[2]), "r"(a[3]), "r"(b0), "r"(b1));
}
__device__ __forceinline__ void ldsm_x4(uint32_t* r, uint32_t saddr) {
    asm volatile(
        "ldmatrix.sync.aligned.m8n8.x4.shared.b16 {%0,%1,%2,%3}, [%4];"
        : "=r"(r[0]), "=r"(r[1]), "=r"(r[2]), "=r"(r[3]) : "r"(saddr));
}
__device__ __forceinline__ void cp_async16(uint32_t saddr, const void* gptr) {
    asm volatile("cp.async.cg.shared.global [%0], [%1], 16;\n"
                 :: "r"(saddr), "l"(gptr));
}
__device__ __forceinline__ void cp_commit() {
    asm volatile("cp.async.commit_group;\n");
}
__device__ __forceinline__ void cp_wait1() {
    asm volatile("cp.async.wait_group 1;\n" ::: "memory");
}
__device__ __forceinline__ void cp_wait0() {
    asm volatile("cp.async.wait_group 0;\n" ::: "memory");
}

// ---------------------------------------------------------------------------
__global__ void round4_kernel(const float* __restrict__ src,
                              float* __restrict__ dst) {
    size_t i = ((size_t)blockIdx.x * 256 + threadIdx.x) * 4;
    float4 v = *(const float4*)(src + i);
    *(float4*)(dst + i) = make_float4(tf32_round(v.x), tf32_round(v.y),
                                      tf32_round(v.z), tf32_round(v.w));
}

// ---------------------------------------------------------------------------
// Pure cp.async tf32 GEMM (pre-rounded operands), LDSM fragment loads.
// MODE 0: Q proj, 3: O proj. BM=BN=128, BK=32, 3-stage pipeline. (R12)
// ---------------------------------------------------------------------------
template <int MODE>
__global__ void __launch_bounds__(256, 2)
async_gemm_kernel(const float* __restrict__ bias, float* __restrict__ Cout) {
    extern __shared__ float dsm[];
    constexpr int KS = 36;
    constexpr int STG = 128 * KS;
    constexpr int NKI = D_MODEL / 32;
    const uint32_t smem_u32 = (uint32_t)__cvta_generic_to_shared(dsm);

    const int tid = threadIdx.x;
    const int lane = tid & 31, warp = tid >> 5;
    const int gid = lane >> 2, tig = lane & 3;

    const int m0 = blockIdx.y * 128;
    const int n_base = blockIdx.x * 128;
    const float* A = (MODE == 0) ? g_qr : g_ctx;
    const float* W = g_rw + (size_t)((MODE == 0) ? 0 : 1) * D_MODEL * D_MODEL;

    const int wm = (warp >> 1) * 32;
    const int wn = (warp & 1) * 64;

    float acc[2][8][4] = {};

    auto CP = [&](int step) {
        int st = step % 3;
#pragma unroll
        for (int i = 0; i < 4; i++) {
            int idx = tid + i * 256;
            int row = idx >> 3, kc = (idx & 7) * 4;
            cp_async16(smem_u32 + (uint32_t)(st * STG + row * KS + kc) * 4,
                       A + (size_t)(m0 + row) * D_MODEL + step * 32 + kc);
        }
#pragma unroll
        for (int i = 0; i < 4; i++) {
            int idx = tid + i * 256;
            int row = idx >> 3, kc = (idx & 7) * 4;
            cp_async16(smem_u32 + (uint32_t)(3 * STG + st * STG + row * KS + kc) * 4,
                       W + (size_t)(n_base + row) * D_MODEL + step * 32 + kc);
        }
        cp_commit();
    };

    const int l15 = lane & 15;
    const int akh = (lane >> 4) * 4;
    const uint32_t aOff = (uint32_t)(((wm + l15) * KS) + akh) * 4;
    const int wrow = wn + ((lane >> 4) << 3) + (lane & 7);
    const int wkh = ((lane >> 3) & 1) * 4;
    const uint32_t wOff = (uint32_t)((wrow * KS) + wkh) * 4;

    auto MMA = [&](int st) {
        uint32_t aB = smem_u32 + (uint32_t)(st * STG) * 4 + aOff;
        uint32_t wB = smem_u32 + (uint32_t)((3 + st) * STG) * 4 + wOff;
#pragma unroll
        for (int ks = 0; ks < 32; ks += 8) {
            uint32_t a0[4], a1[4];
            ldsm_x4(a0, aB + ks * 4);
            ldsm_x4(a1, aB + 16 * KS * 4 + ks * 4);
#pragma unroll
            for (int p = 0; p < 4; p++) {
                uint32_t w[4];
                ldsm_x4(w, wB + (uint32_t)(p * 16 * KS + ks) * 4);
                mma_tf32(acc[0][2 * p],     a0, w[0], w[1]);
                mma_tf32(acc[1][2 * p],     a1, w[0], w[1]);
                mma_tf32(acc[0][2 * p + 1], a0, w[2], w[3]);
                mma_tf32(acc[1][2 * p + 1], a1, w[2], w[3]);
            }
        }
    };

    CP(0);
    CP(1);
    cp_wait1();
    __syncthreads();
#pragma unroll 1
    for (int c = 0; c < NKI; c++) {
        if (c + 2 < NKI) CP(c + 2);
        MMA(c % 3);
        if (c + 2 < NKI) cp_wait1(); else cp_wait0();
        __syncthreads();
    }

#pragma unroll
    for (int mi = 0; mi < 2; mi++) {
#pragma unroll
        for (int ni = 0; ni < 8; ni++) {
#pragma unroll
            for (int r = 0; r < 4; r++) {
                int ml = wm + mi * 16 + gid + ((r >> 1) ? 8 : 0);
                int nl = wn + ni * 8 + 2 * tig + (r & 1);
                float v = acc[mi][ni][r];
                if (MODE == 0) {
                    int m = m0 + ml;
                    int n = n_base + nl;
                    int bb = m >> 11, tq = m & 2047;
                    int hh = n >> 6, d = n & 63;
                    g_Qh[(((size_t)bb * N_HEAD + hh) * TQ + tq) * HEAD_DIM + d] =
                        v + bias[n];
                } else {
                    Cout[(size_t)(m0 + ml) * D_MODEL + n_base + nl] =
                        v + bias[n_base + nl];
                }
            }
        }
    }
}

// ---------------------------------------------------------------------------
// R12 tf32 GEMM for sliced K/V projections (LDSM). MODE 1: K, 2: V. BN=64.
// ---------------------------------------------------------------------------
template <int BN, int MODE>
__global__ void __launch_bounds__(256, 2)
tf32_gemm_kernel(const float* __restrict__ Ain,
                 const float* __restrict__ W,
                 const float* __restrict__ bias) {
    extern __shared__ float dsm[];
    constexpr int KS = 36;
    constexpr int ASTAGE = 128 * KS;
    constexpr int WSTAGE = BN * KS;
    float* Asb[2] = {dsm, dsm + ASTAGE + WSTAGE};
    float* Wsb[2] = {dsm + ASTAGE, dsm + 2 * ASTAGE + WSTAGE};
    const uint32_t smem_u32 = (uint32_t)__cvta_generic_to_shared(dsm);

    const int tid = threadIdx.x;
    const int lane = tid & 31, warp = tid >> 5;
    const int gid = lane >> 2, tig = lane & 3;

    const int bh = blockIdx.y;
    const int b = bh >> 4, h = bh & 15;
    const int m0 = blockIdx.x * 128;
    const float* A = Ain + (size_t)b * TK * D_MODEL;
    const int n_base = h * 64;

    const int wm = (warp >> 1) * 32;
    const int wn = (warp & 1) * (BN / 2);
    constexpr int NF = BN / 16;
    constexpr int WL = BN / 32;

    float acc[2][NF][4] = {};
    float4 avS[4];
    float4 wvS[WL];

    auto LOAD = [&](int k0) {
#pragma unroll
        for (int i = 0; i < 4; i++) {
            int idx = tid + i * 256;
            int row = idx >> 3, kc = (idx & 7) * 4;
            int grow = h + STRIDE * (m0 + row);
            avS[i] = *(const float4*)(A + (size_t)grow * D_MODEL + k0 + kc);
        }
#pragma unroll
        for (int i = 0; i < WL; i++) {
            int idx = tid + i * 256;
            int nrow = idx >> 3, kc = (idx & 7) * 4;
            wvS[i] = *(const float4*)(W + (size_t)(n_base + nrow) * D_MODEL + k0 + kc);
        }
    };
    auto STORE = [&](int s) {
        float* As = Asb[s];
        float* Ws = Wsb[s];
#pragma unroll
        for (int i = 0; i < 4; i++) {
            int idx = tid + i * 256;
            int row = idx >> 3, kc = (idx & 7) * 4;
            float4 r = make_float4(tf32_round(avS[i].x), tf32_round(avS[i].y),
                                   tf32_round(avS[i].z), tf32_round(avS[i].w));
            *(float4*)&As[row * KS + kc] = r;
        }
#pragma unroll
        for (int i = 0; i < WL; i++) {
            int idx = tid + i * 256;
            int nrow = idx >> 3, kc = (idx & 7) * 4;
            float4 r = make_float4(tf32_round(wvS[i].x), tf32_round(wvS[i].y),
                                   tf32_round(wvS[i].z), tf32_round(wvS[i].w));
            *(float4*)&Ws[nrow * KS + kc] = r;
        }
    };

    const int l15 = lane & 15;
    const int akh = (lane >> 4) * 4;
    const uint32_t aOff = (uint32_t)(((wm + l15) * KS) + akh) * 4;
    const int wrow = wn + ((lane >> 4) << 3) + (lane & 7);
    const int wkh = ((lane >> 3) & 1) * 4;
    const uint32_t wOff = (uint32_t)((wrow * KS) + wkh) * 4;

    auto MMA = [&](int s) {
        uint32_t aB = smem_u32 + (uint32_t)(s * (ASTAGE + WSTAGE)) * 4 + aOff;
        uint32_t wB = smem_u32 +
                      (uint32_t)(ASTAGE + s * (ASTAGE + WSTAGE)) * 4 + wOff;
#pragma unroll
        for (int ks = 0; ks < 32; ks += 8) {
            uint32_t a0[4], a1[4];
            ldsm_x4(a0, aB + ks * 4);
            ldsm_x4(a1, aB + 16 * KS * 4 + ks * 4);
#pragma unroll
            for (int p = 0; p < NF / 2; p++) {
                uint32_t w[4];
                ldsm_x4(w, wB + (uint32_t)(p * 16 * KS + ks) * 4);
                mma_tf32(acc[0][2 * p],     a0, w[0], w[1]);
                mma_tf32(acc[1][2 * p],     a1, w[0], w[1]);
                mma_tf32(acc[0][2 * p + 1], a0, w[2], w[3]);
                mma_tf32(acc[1][2 * p + 1], a1, w[2], w[3]);
            }
        }
    };

    LOAD(0);
    STORE(0);
    __syncthreads();
    int s = 0;
#pragma unroll 1
    for (int k0 = 32; k0 < D_MODEL; k0 += 32) {
        LOAD(k0);
        MMA(s);
        STORE(s ^ 1);
        __syncthreads();
        s ^= 1;
    }
    MMA(s);

#pragma unroll
    for (int mi = 0; mi < 2; mi++) {
#pragma unroll
        for (int ni = 0; ni < NF; ni++) {
#pragma unroll
            for (int r = 0; r < 4; r++) {
                int ml = wm + mi * 16 + gid + ((r >> 1) ? 8 : 0);
                int nl = wn + ni * 8 + 2 * tig + (r & 1);
                float v = acc[mi][ni][r] + bias[n_base + nl];
                if (MODE == 1)
                    g_Kh[((size_t)bh * L_CTX + m0 + ml) * HEAD_DIM + nl] = v;
                else
                    g_Vh[((size_t)bh * L_CTX + m0 + ml) * HEAD_DIM + nl] = v;
            }
        }
    }
}

// ---------------------------------------------------------------------------
// Flash attention: q-tile 128, 256 threads / 8 warps, warp owns 16 rows.
// Layouts identical to R10/R12; mg = warp. P has 8 per-warp stripes.
// ---------------------------------------------------------------------------
#define AT_THREADS 256
#define WOFF_QH  0
#define WOFF_QL  4096
#define WOFF_KH  8192
#define WOFF_KL  10272
#define WOFF_VF  12352
#define WOFF_P   17472
#define WOFF_MSK (17472 + 8 * 16 * 68)
#define AT_SMEM_BYTES ((WOFF_MSK + 512) * 4)

__global__ void __launch_bounds__(256, 2)
attn_kernel(const int* __restrict__ mask) {
    extern __shared__ float smf[];
    uint32_t* QH = (uint32_t*)smf + WOFF_QH;
    uint32_t* QL = (uint32_t*)smf + WOFF_QL;
    uint32_t* KH = (uint32_t*)smf + WOFF_KH;
    uint32_t* KL = (uint32_t*)smf + WOFF_KL;
    float* Vf = smf + WOFF_VF;
    float* Pw = smf + WOFF_P;
    int*   msk = (int*)(smf + WOFF_MSK);

    const int bh = blockIdx.y;
    const int b = bh >> 4, h = bh & 15;
    const int q0 = blockIdx.x * 128;
    const int tid = threadIdx.x;
    const int lane = tid & 31, warp = tid >> 5;   // warp = mg (0..7)
    const int gid = lane >> 2, tig = lane & 3;

    for (int i = tid; i < L_CTX; i += AT_THREADS)
        msk[i] = mask[(size_t)b * TK + h + STRIDE * i];

    // ---- Q tile -> bf16 hi/lo fragment smem (built once) ----
    const float* Qb = g_Qh + ((size_t)bh * TQ + q0) * HEAD_DIM;
#pragma unroll
    for (int i = 0; i < 8; i++) {
        int idx = tid + i * AT_THREADS;     // 0..2047
        int row = idx >> 4;                 // 0..127
        int dc = (idx & 15) * 4;
        float4 v = *(const float4*)(Qb + row * 64 + dc);
        int mg = row >> 4;
        int rl = row & 15;
        int rowhalf = rl >> 3, gidr = rl & 7;
        int ks = dc >> 4;
        int khalf = ((dc & 15) >= 8) ? 1 : 0;
        int tigw = (dc & 7) >> 1;
        int j = (khalf << 1) | rowhalf;
        uint32_t h0 = pack_bf16x2(v.x, v.y);
        uint32_t h1 = pack_bf16x2(v.z, v.w);
        float h0a = __uint_as_float(h0 << 16);
        float h0b = __uint_as_float(h0 & 0xffff0000u);
        float h1a = __uint_as_float(h1 << 16);
        float h1b = __uint_as_float(h1 & 0xffff0000u);
        uint32_t l0 = pack_bf16x2(v.x - h0a, v.y - h0b);
        uint32_t l1 = pack_bf16x2(v.z - h1a, v.w - h1b);
        int base = ((ks * 8 + mg) * 32 + gidr * 4);
        QH[(base + tigw) * 4 + j] = h0;
        QH[(base + tigw + 1) * 4 + j] = h1;
        QL[(base + tigw) * 4 + j] = l0;
        QL[(base + tigw + 1) * 4 + j] = l1;
    }

    const float* Kb = g_Kh + (size_t)bh * L_CTX * HEAD_DIM;
    const float* Vb = g_Vh + (size_t)bh * L_CTX * HEAD_DIM;
    float* Pp = Pw + warp * (16 * 68);

    float oacc[8][4] = {};
    float M0 = -1e30f, M1 = -1e30f;
    float L0 = 0.f, L1 = 0.f;

#pragma unroll 1
    for (int lt = 0; lt < 8; lt++) {
        __syncthreads();
        // ---- K (bf16 hi/lo packed) + V (tf32) tile load ----
#pragma unroll
        for (int i = 0; i < 4; i++) {
            int idx = tid + i * AT_THREADS;
            int r = idx >> 4;               // key row 0..63
            int dc = (idx & 15) * 4;
            float4 kv = *(const float4*)(Kb + (size_t)(lt * 64 + r) * 64 + dc);
            int ks = dc >> 4;
            int khalf = ((dc & 15) >= 8) ? 1 : 0;
            int tigw = (dc & 7) >> 1;
            uint32_t h0 = pack_bf16x2(kv.x, kv.y);
            uint32_t h1 = pack_bf16x2(kv.z, kv.w);
            float h0a = __uint_as_float(h0 << 16);
            float h0b = __uint_as_float(h0 & 0xffff0000u);
            float h1a = __uint_as_float(h1 << 16);
            float h1b = __uint_as_float(h1 & 0xffff0000u);
            uint32_t l0 = pack_bf16x2(kv.x - h0a, kv.y - h0b);
            uint32_t l1 = pack_bf16x2(kv.z - h1a, kv.w - h1b);
            int kb = ks * 520 + r * 8 + khalf;
            KH[kb + tigw * 2] = h0;
            KH[kb + (tigw + 1) * 2] = h1;
            KL[kb + tigw * 2] = l0;
            KL[kb + (tigw + 1) * 2] = l1;

            float4 vv = *(const float4*)(Vb + (size_t)(lt * 64 + r) * 64 + dc);
            float vl[4] = {vv.x, vv.y, vv.z, vv.w};
            int vks = r >> 3, vkh = (r >> 2) & 1;
            int vte = ((r & 3) + vks) & 3;
#pragma unroll
            for (int e = 0; e < 4; e++)
                Vf[((vks * 64 + (dc + e)) * 5 + vte) * 2 + vkh] = tf32_round(vl[e]);
        }
        __syncthreads();

        // ---- S = Q K^T : bf16 k16, 3-term split ----
        float sacc[8][4] = {};
#pragma unroll
        for (int ks = 0; ks < 4; ks++) {
            int qb = ((ks * 8 + warp) * 32 + lane) * 4;
            uint4 qh = *(const uint4*)&QH[qb];
            uint4 ql = *(const uint4*)&QL[qb];
#pragma unroll
            for (int ni = 0; ni < 8; ni++) {
                int n = ni * 8 + gid;
                int kb = ks * 520 + n * 8 + tig * 2;
                uint2 bh2 = *(const uint2*)&KH[kb];
                uint2 bl2 = *(const uint2*)&KL[kb];
                mma_bf16(sacc[ni], (const uint32_t*)&qh, bh2.x, bh2.y);
                mma_bf16(sacc[ni], (const uint32_t*)&qh, bl2.x, bl2.y);
                mma_bf16(sacc[ni], (const uint32_t*)&ql, bh2.x, bh2.y);
            }
        }

        // ---- mask + online softmax (warp-local 16 rows) ----
        float mt0 = -1e30f, mt1 = -1e30f;
#pragma unroll
        for (int ni = 0; ni < 8; ni++) {
            int c = lt * 64 + ni * 8 + 2 * tig;
            bool z0 = (msk[c] == 0), z1 = (msk[c + 1] == 0);
            sacc[ni][0] = z0 ? -1e9f : sacc[ni][0] * 0.125f;
            sacc[ni][1] = z1 ? -1e9f : sacc[ni][1] * 0.125f;
            sacc[ni][2] = z0 ? -1e9f : sacc[ni][2] * 0.125f;
            sacc[ni][3] = z1 ? -1e9f : sacc[ni][3] * 0.125f;
            mt0 = fmaxf(mt0, fmaxf(sacc[ni][0], sacc[ni][1]));
            mt1 = fmaxf(mt1, fmaxf(sacc[ni][2], sacc[ni][3]));
        }
        mt0 = fmaxf(mt0, __shfl_xor_sync(0xffffffffu, mt0, 1));
        mt0 = fmaxf(mt0, __shfl_xor_sync(0xffffffffu, mt0, 2));
        mt1 = fmaxf(mt1, __shfl_xor_sync(0xffffffffu, mt1, 1));
        mt1 = fmaxf(mt1, __shfl_xor_sync(0xffffffffu, mt1, 2));

        float Mn0 = fmaxf(M0, mt0), Mn1 = fmaxf(M1, mt1);
        float f0 = __expf(M0 - Mn0), f1 = __expf(M1 - Mn1);
        float s0 = 0.f, s1 = 0.f;
#pragma unroll
        for (int ni = 0; ni < 8; ni++) {
            int cc = ni * 8 + 2 * tig;
            float p00 = __expf(sacc[ni][0] - Mn0);
            float p01 = __expf(sacc[ni][1] - Mn0);
            float p10 = __expf(sacc[ni][2] - Mn1);
            float p11 = __expf(sacc[ni][3] - Mn1);
            s0 += p00 + p01; s1 += p10 + p11;
            Pp[gid * 68 + cc]           = tf32_round(p00);
            Pp[gid * 68 + cc + 1]       = tf32_round(p01);
            Pp[(gid + 8) * 68 + cc]     = tf32_round(p10);
            Pp[(gid + 8) * 68 + cc + 1] = tf32_round(p11);
        }
        s0 += __shfl_xor_sync(0xffffffffu, s0, 1);
        s0 += __shfl_xor_sync(0xffffffffu, s0, 2);
        s1 += __shfl_xor_sync(0xffffffffu, s1, 1);
        s1 += __shfl_xor_sync(0xffffffffu, s1, 2);
        L0 = L0 * f0 + s0;
        L1 = L1 * f1 + s1;
        M0 = Mn0; M1 = Mn1;
#pragma unroll
        for (int ni = 0; ni < 8; ni++) {
            oacc[ni][0] *= f0; oacc[ni][1] *= f0;
            oacc[ni][2] *= f1; oacc[ni][3] *= f1;
        }
        __syncwarp();

        // ---- O += P V ----
#pragma unroll
        for (int ks = 0; ks < 8; ks++) {
            uint32_t a[4];
            a[0] = __float_as_uint(Pp[gid * 68 + ks * 8 + tig]);
            a[1] = __float_as_uint(Pp[(gid + 8) * 68 + ks * 8 + tig]);
            a[2] = __float_as_uint(Pp[gid * 68 + ks * 8 + tig + 4]);
            a[3] = __float_as_uint(Pp[(gid + 8) * 68 + ks * 8 + tig + 4]);
#pragma unroll
            for (int ni = 0; ni < 8; ni++) {
                int n = ni * 8 + gid;
                int ip = ((ks * 64 + n) * 5 + ((tig + ks) & 3)) * 2;
                float2 bv = *(const float2*)&Vf[ip];
                mma_tf32(oacc[ni], a,
                         __float_as_uint(bv.x), __float_as_uint(bv.y));
            }
        }
        __syncwarp();
    }

    // ---- epilogue ----
    float inv0 = 1.0f / L0, inv1 = 1.0f / L1;
    int r0 = q0 + warp * 16 + gid;
#pragma unroll
    for (int ni = 0; ni < 8; ni++) {
        int col = h * 64 + ni * 8 + 2 * tig;
        size_t base0 = ((size_t)b * TQ + r0) * D_MODEL + col;
        *(float2*)&g_ctx[base0] =
            make_float2(tf32_round(oacc[ni][0] * inv0),
                        tf32_round(oacc[ni][1] * inv0));
        *(float2*)&g_ctx[base0 + (size_t)8 * D_MODEL] =
            make_float2(tf32_round(oacc[ni][2] * inv1),
                        tf32_round(oacc[ni][3] * inv1));
    }
}

// ---------------------------------------------------------------------------
extern "C" void kernel_launch(void* const* d_in, const int* in_sizes, int n_in,
                              void* d_out, int out_size) {
    const float* q        = (const float*)d_in[0];
    const float* k        = (const float*)d_in[1];
    const float* v        = (const float*)d_in[2];
    const int*   src_mask = (const int*)d_in[3];
    const float* w_q      = (const float*)d_in[4];
    const float* b_q      = (const float*)d_in[5];
    const float* w_k      = (const float*)d_in[6];
    const float* b_k      = (const float*)d_in[7];
    const float* w_v      = (const float*)d_in[8];
    const float* b_v      = (const float*)d_in[9];
    const float* w_o      = (const float*)d_in[10];
    const float* b_o      = (const float*)d_in[11];
    float* out = (float*)d_out;

    constexpr int ASM = 3 * (128 * 36 + 128 * 36) * 4;       // 110592
    constexpr int PSM_64 = 2 * (128 * 36 + 64 * 36) * 4;     // 55296

    cudaFuncSetAttribute(attn_kernel,
                         cudaFuncAttributeMaxDynamicSharedMemorySize,
                         AT_SMEM_BYTES);
    cudaFuncSetAttribute(async_gemm_kernel<0>,
                         cudaFuncAttributeMaxDynamicSharedMemorySize, ASM);
    cudaFuncSetAttribute(async_gemm_kernel<3>,
                         cudaFuncAttributeMaxDynamicSharedMemorySize, ASM);
    cudaFuncSetAttribute(tf32_gemm_kernel<64, 1>,
                         cudaFuncAttributeMaxDynamicSharedMemorySize, PSM_64);
    cudaFuncSetAttribute(tf32_gemm_kernel<64, 2>,
                         cudaFuncAttributeMaxDynamicSharedMemorySize, PSM_64);

    float* d_qr = nullptr;  cudaGetSymbolAddress((void**)&d_qr, g_qr);
    float* d_rw = nullptr;  cudaGetSymbolAddress((void**)&d_rw, g_rw);
    round4_kernel<<<(B_SZ * TQ * D_MODEL) / 1024, 256>>>(q, d_qr);
    round4_kernel<<<(D_MODEL * D_MODEL) / 1024, 256>>>(w_q, d_rw);
    round4_kernel<<<(D_MODEL * D_MODEL) / 1024, 256>>>(
        w_o, d_rw + (size_t)D_MODEL * D_MODEL);

    async_gemm_kernel<0><<<dim3(8, 64), 256, ASM>>>(b_q, nullptr);
    tf32_gemm_kernel<64, 1><<<dim3(L_CTX / 128, B_SZ * N_HEAD), 256,
                              PSM_64>>>(k, w_k, b_k);
    tf32_gemm_kernel<64, 2><<<dim3(L_CTX / 128, B_SZ * N_HEAD), 256,
                              PSM_64>>>(v, w_v, b_v);

    attn_kernel<<<dim3(TQ / 128, B_SZ * N_HEAD), 256, AT_SMEM_BYTES>>>(src_mask);

    async_gemm_kernel<3><<<dim3(8, 64), 256, ASM>>>(b_o, out);
}

// round 14
// speedup vs baseline: 1.0030x; 1.0030x over previous
#include <cuda_runtime.h>
#include <cstdint>

#define D_MODEL 1024
#define N_HEAD 16
#define HEAD_DIM 64
#define B_SZ 4
#define TQ 2048
#define TK 8192
#define STRIDE 16
#define L_CTX 512

__device__ float g_Qh[(size_t)B_SZ * N_HEAD * TQ * HEAD_DIM];
__device__ float g_Kh[(size_t)B_SZ * N_HEAD * L_CTX * HEAD_DIM];
__device__ float g_Vh[(size_t)B_SZ * N_HEAD * L_CTX * HEAD_DIM];
__device__ float g_ctx[(size_t)B_SZ * TQ * D_MODEL];
__device__ float g_qr[(size_t)B_SZ * TQ * D_MODEL];
__device__ float g_rw[(size_t)2 * D_MODEL * D_MODEL];
// pre-formatted K/V fragment buffers: per (bh, lt) segment
__device__ __align__(16) uint32_t g_KHg[(size_t)64 * 8 * 2080];
__device__ __align__(16) uint32_t g_KLg[(size_t)64 * 8 * 2080];
__device__ __align__(16) float    g_VFg[(size_t)64 * 8 * 5120];

// ---------------------------------------------------------------------------
__device__ __forceinline__ float tf32_round(float x) {
    uint32_t u;
    asm("cvt.rna.tf32.f32 %0, %1;" : "=r"(u) : "f"(x));
    return __uint_as_float(u);
}
__device__ __forceinline__ uint32_t pack_bf16x2(float lo, float hi) {
    uint32_t r;
    asm("cvt.rn.bf16x2.f32 %0, %1, %2;" : "=r"(r) : "f"(hi), "f"(lo));
    return r;
}
__device__ __forceinline__ void mma_tf32(float* c, const uint32_t* a,
                                         uint32_t b0, uint32_t b1) {
    asm volatile(
        "mma.sync.aligned.m16n8k8.row.col.f32.tf32.tf32.f32 "
        "{%0,%1,%2,%3}, {%4,%5,%6,%7}, {%8,%9}, {%0,%1,%2,%3};\n"
        : "+f"(c[0]), "+f"(c[1]), "+f"(c[2]), "+f"(c[3])
        : "r"(a[0]), "r"(a[1]), "r"(a[2]), "r"(a[3]), "r"(b0), "r"(b1));
}
__device__ __forceinline__ void mma_bf16(float* c, const uint32_t* a,
                                         uint32_t b0, uint32_t b1) {
    asm volatile(
        "mma.sync.aligned.m16n8k16.row.col.f32.bf16.bf16.f32 "
        "{%0,%1,%2,%3}, {%4,%5,%6,%7}, {%8,%9}, {%0,%1,%2,%3};\n"
        : "+f"(c[0]), "+f"(c[1]), "+f"(c[2]), "+f"(c[3])
        : "r"(a[0]), "r"(a[1]), "r"(a[2]), "r"(a[3]), "r"(b0), "r"(b1));
}
__device__ __forceinline__ void ldsm_x4(uint32_t* r, uint32_t saddr) {
    asm volatile(
        "ldmatrix.sync.aligned.m8n8.x4.shared.b16 {%0,%1,%2,%3}, [%4];"
        : "=r"(r[0]), "=r"(r[1]), "=r"(r[2]), "=r"(r[3]) : "r"(saddr));
}
__device__ __forceinline__ void cp_async16(uint32_t saddr, const void* gptr) {
    asm volatile("cp.async.cg.shared.global [%0], [%1], 16;\n"
                 :: "r"(saddr), "l"(gptr));
}
__device__ __forceinline__ void cp_commit() {
    asm volatile("cp.async.commit_group;\n");
}
__device__ __forceinline__ void cp_wait1() {
    asm volatile("cp.async.wait_group 1;\n" ::: "memory");
}
__device__ __forceinline__ void cp_wait0() {
    asm volatile("cp.async.wait_group 0;\n" ::: "memory");
}

// ---------------------------------------------------------------------------
__global__ void round4_kernel(const float* __restrict__ src,
                              float* __restrict__ dst) {
    size_t i = ((size_t)blockIdx.x * 256 + threadIdx.x) * 4;
    float4 v = *(const float4*)(src + i);
    *(float4*)(dst + i) = make_float4(tf32_round(v.x), tf32_round(v.y),
                                      tf32_round(v.z), tf32_round(v.w));
}

// ---------------------------------------------------------------------------
// Format K/V tiles once into fragment-ready global buffers.
// One block per (lt, bh); conversion code identical to R12 attn tile load.
// ---------------------------------------------------------------------------
__global__ void __launch_bounds__(128)
fmt_kv_kernel() {
    const int lt = blockIdx.x, bh = blockIdx.y;
    const int tid = threadIdx.x;
    const float* Kb = g_Kh + (size_t)bh * L_CTX * HEAD_DIM;
    const float* Vb = g_Vh + (size_t)bh * L_CTX * HEAD_DIM;
    uint32_t* KH = g_KHg + (size_t)(bh * 8 + lt) * 2080;
    uint32_t* KL = g_KLg + (size_t)(bh * 8 + lt) * 2080;
    float*    VF = g_VFg + (size_t)(bh * 8 + lt) * 5120;

#pragma unroll
    for (int i = 0; i < 8; i++) {
        int idx = tid + i * 128;
        int r = idx >> 4;               // key row 0..63
        int dc = (idx & 15) * 4;
        float4 kv = *(const float4*)(Kb + (size_t)(lt * 64 + r) * 64 + dc);
        int ks = dc >> 4;
        int khalf = ((dc & 15) >= 8) ? 1 : 0;
        int tigw = (dc & 7) >> 1;
        uint32_t h0 = pack_bf16x2(kv.x, kv.y);
        uint32_t h1 = pack_bf16x2(kv.z, kv.w);
        float h0a = __uint_as_float(h0 << 16);
        float h0b = __uint_as_float(h0 & 0xffff0000u);
        float h1a = __uint_as_float(h1 << 16);
        float h1b = __uint_as_float(h1 & 0xffff0000u);
        uint32_t l0 = pack_bf16x2(kv.x - h0a, kv.y - h0b);
        uint32_t l1 = pack_bf16x2(kv.z - h1a, kv.w - h1b);
        int kb = ks * 520 + r * 8 + khalf;
        KH[kb + tigw * 2] = h0;
        KH[kb + (tigw + 1) * 2] = h1;
        KL[kb + tigw * 2] = l0;
        KL[kb + (tigw + 1) * 2] = l1;

        float4 vv = *(const float4*)(Vb + (size_t)(lt * 64 + r) * 64 + dc);
        float vl[4] = {vv.x, vv.y, vv.z, vv.w};
        int vks = r >> 3, vkh = (r >> 2) & 1;
        int vte = ((r & 3) + vks) & 3;
#pragma unroll
        for (int e = 0; e < 4; e++)
            VF[((vks * 64 + (dc + e)) * 5 + vte) * 2 + vkh] = tf32_round(vl[e]);
    }
}

// ---------------------------------------------------------------------------
// Pure cp.async tf32 GEMM (pre-rounded operands), LDSM fragment loads. (R12)
// MODE 0: Q proj, 3: O proj.
// ---------------------------------------------------------------------------
template <int MODE>
__global__ void __launch_bounds__(256, 2)
async_gemm_kernel(const float* __restrict__ bias, float* __restrict__ Cout) {
    extern __shared__ float dsm[];
    constexpr int KS = 36;
    constexpr int STG = 128 * KS;
    constexpr int NKI = D_MODEL / 32;
    const uint32_t smem_u32 = (uint32_t)__cvta_generic_to_shared(dsm);

    const int tid = threadIdx.x;
    const int lane = tid & 31, warp = tid >> 5;
    const int gid = lane >> 2, tig = lane & 3;

    const int m0 = blockIdx.y * 128;
    const int n_base = blockIdx.x * 128;
    const float* A = (MODE == 0) ? g_qr : g_ctx;
    const float* W = g_rw + (size_t)((MODE == 0) ? 0 : 1) * D_MODEL * D_MODEL;

    const int wm = (warp >> 1) * 32;
    const int wn = (warp & 1) * 64;

    float acc[2][8][4] = {};

    auto CP = [&](int step) {
        int st = step % 3;
#pragma unroll
        for (int i = 0; i < 4; i++) {
            int idx = tid + i * 256;
            int row = idx >> 3, kc = (idx & 7) * 4;
            cp_async16(smem_u32 + (uint32_t)(st * STG + row * KS + kc) * 4,
                       A + (size_t)(m0 + row) * D_MODEL + step * 32 + kc);
        }
#pragma unroll
        for (int i = 0; i < 4; i++) {
            int idx = tid + i * 256;
            int row = idx >> 3, kc = (idx & 7) * 4;
            cp_async16(smem_u32 + (uint32_t)(3 * STG + st * STG + row * KS + kc) * 4,
                       W + (size_t)(n_base + row) * D_MODEL + step * 32 + kc);
        }
        cp_commit();
    };

    const int l15 = lane & 15;
    const int akh = (lane >> 4) * 4;
    const uint32_t aOff = (uint32_t)(((wm + l15) * KS) + akh) * 4;
    const int wrow = wn + ((lane >> 4) << 3) + (lane & 7);
    const int wkh = ((lane >> 3) & 1) * 4;
    const uint32_t wOff = (uint32_t)((wrow * KS) + wkh) * 4;

    auto MMA = [&](int st) {
        uint32_t aB = smem_u32 + (uint32_t)(st * STG) * 4 + aOff;
        uint32_t wB = smem_u32 + (uint32_t)((3 + st) * STG) * 4 + wOff;
#pragma unroll
        for (int ks = 0; ks < 32; ks += 8) {
            uint32_t a0[4], a1[4];
            ldsm_x4(a0, aB + ks * 4);
            ldsm_x4(a1, aB + 16 * KS * 4 + ks * 4);
#pragma unroll
            for (int p = 0; p < 4; p++) {
                uint32_t w[4];
                ldsm_x4(w, wB + (uint32_t)(p * 16 * KS + ks) * 4);
                mma_tf32(acc[0][2 * p],     a0, w[0], w[1]);
                mma_tf32(acc[1][2 * p],     a1, w[0], w[1]);
                mma_tf32(acc[0][2 * p + 1], a0, w[2], w[3]);
                mma_tf32(acc[1][2 * p + 1], a1, w[2], w[3]);
            }
        }
    };

    CP(0);
    CP(1);
    cp_wait1();
    __syncthreads();
#pragma unroll 1
    for (int c = 0; c < NKI; c++) {
        if (c + 2 < NKI) CP(c + 2);
        MMA(c % 3);
        if (c + 2 < NKI) cp_wait1(); else cp_wait0();
        __syncthreads();
    }

#pragma unroll
    for (int mi = 0; mi < 2; mi++) {
#pragma unroll
        for (int ni = 0; ni < 8; ni++) {
#pragma unroll
            for (int r = 0; r < 4; r++) {
                int ml = wm + mi * 16 + gid + ((r >> 1) ? 8 : 0);
                int nl = wn + ni * 8 + 2 * tig + (r & 1);
                float v = acc[mi][ni][r];
                if (MODE == 0) {
                    int m = m0 + ml;
                    int n = n_base + nl;
                    int bb = m >> 11, tq = m & 2047;
                    int hh = n >> 6, d = n & 63;
                    g_Qh[(((size_t)bb * N_HEAD + hh) * TQ + tq) * HEAD_DIM + d] =
                        v + bias[n];
                } else {
                    Cout[(size_t)(m0 + ml) * D_MODEL + n_base + nl] =
                        v + bias[n_base + nl];
                }
            }
        }
    }
}

// ---------------------------------------------------------------------------
// R12 tf32 GEMM for sliced K/V projections (LDSM). MODE 1: K, 2: V. BN=64.
// ---------------------------------------------------------------------------
template <int BN, int MODE>
__global__ void __launch_bounds__(256, 2)
tf32_gemm_kernel(const float* __restrict__ Ain,
                 const float* __restrict__ W,
                 const float* __restrict__ bias) {
    extern __shared__ float dsm[];
    constexpr int KS = 36;
    constexpr int ASTAGE = 128 * KS;
    constexpr int WSTAGE = BN * KS;
    float* Asb[2] = {dsm, dsm + ASTAGE + WSTAGE};
    float* Wsb[2] = {dsm + ASTAGE, dsm + 2 * ASTAGE + WSTAGE};
    const uint32_t smem_u32 = (uint32_t)__cvta_generic_to_shared(dsm);

    const int tid = threadIdx.x;
    const int lane = tid & 31, warp = tid >> 5;
    const int gid = lane >> 2, tig = lane & 3;

    const int bh = blockIdx.y;
    const int b = bh >> 4, h = bh & 15;
    const int m0 = blockIdx.x * 128;
    const float* A = Ain + (size_t)b * TK * D_MODEL;
    const int n_base = h * 64;

    const int wm = (warp >> 1) * 32;
    const int wn = (warp & 1) * (BN / 2);
    constexpr int NF = BN / 16;
    constexpr int WL = BN / 32;

    float acc[2][NF][4] = {};
    float4 avS[4];
    float4 wvS[WL];

    auto LOAD = [&](int k0) {
#pragma unroll
        for (int i = 0; i < 4; i++) {
            int idx = tid + i * 256;
            int row = idx >> 3, kc = (idx & 7) * 4;
            int grow = h + STRIDE * (m0 + row);
            avS[i] = *(const float4*)(A + (size_t)grow * D_MODEL + k0 + kc);
        }
#pragma unroll
        for (int i = 0; i < WL; i++) {
            int idx = tid + i * 256;
            int nrow = idx >> 3, kc = (idx & 7) * 4;
            wvS[i] = *(const float4*)(W + (size_t)(n_base + nrow) * D_MODEL + k0 + kc);
        }
    };
    auto STORE = [&](int s) {
        float* As = Asb[s];
        float* Ws = Wsb[s];
#pragma unroll
        for (int i = 0; i < 4; i++) {
            int idx = tid + i * 256;
            int row = idx >> 3, kc = (idx & 7) * 4;
            float4 r = make_float4(tf32_round(avS[i].x), tf32_round(avS[i].y),
                                   tf32_round(avS[i].z), tf32_round(avS[i].w));
            *(float4*)&As[row * KS + kc] = r;
        }
#pragma unroll
        for (int i = 0; i < WL; i++) {
            int idx = tid + i * 256;
            int nrow = idx >> 3, kc = (idx & 7) * 4;
            float4 r = make_float4(tf32_round(wvS[i].x), tf32_round(wvS[i].y),
                                   tf32_round(wvS[i].z), tf32_round(wvS[i].w));
            *(float4*)&Ws[nrow * KS + kc] = r;
        }
    };

    const int l15 = lane & 15;
    const int akh = (lane >> 4) * 4;
    const uint32_t aOff = (uint32_t)(((wm + l15) * KS) + akh) * 4;
    const int wrow = wn + ((lane >> 4) << 3) + (lane & 7);
    const int wkh = ((lane >> 3) & 1) * 4;
    const uint32_t wOff = (uint32_t)((wrow * KS) + wkh) * 4;

    auto MMA = [&](int s) {
        uint32_t aB = smem_u32 + (uint32_t)(s * (ASTAGE + WSTAGE)) * 4 + aOff;
        uint32_t wB = smem_u32 +
                      (uint32_t)(ASTAGE + s * (ASTAGE + WSTAGE)) * 4 + wOff;
#pragma unroll
        for (int ks = 0; ks < 32; ks += 8) {
            uint32_t a0[4], a1[4];
            ldsm_x4(a0, aB + ks * 4);
            ldsm_x4(a1, aB + 16 * KS * 4 + ks * 4);
#pragma unroll
            for (int p = 0; p < NF / 2; p++) {
                uint32_t w[4];
                ldsm_x4(w, wB + (uint32_t)(p * 16 * KS + ks) * 4);
                mma_tf32(acc[0][2 * p],     a0, w[0], w[1]);
                mma_tf32(acc[1][2 * p],     a1, w[0], w[1]);
                mma_tf32(acc[0][2 * p + 1], a0, w[2], w[3]);
                mma_tf32(acc[1][2 * p + 1], a1, w[2], w[3]);
            }
        }
    };

    LOAD(0);
    STORE(0);
    __syncthreads();
    int s = 0;
#pragma unroll 1
    for (int k0 = 32; k0 < D_MODEL; k0 += 32) {
        LOAD(k0);
        MMA(s);
        STORE(s ^ 1);
        __syncthreads();
        s ^= 1;
    }
    MMA(s);

#pragma unroll
    for (int mi = 0; mi < 2; mi++) {
#pragma unroll
        for (int ni = 0; ni < NF; ni++) {
#pragma unroll
            for (int r = 0; r < 4; r++) {
                int ml = wm + mi * 16 + gid + ((r >> 1) ? 8 : 0);
                int nl = wn + ni * 8 + 2 * tig + (r & 1);
                float v = acc[mi][ni][r] + bias[n_base + nl];
                if (MODE == 1)
                    g_Kh[((size_t)bh * L_CTX + m0 + ml) * HEAD_DIM + nl] = v;
                else
                    g_Vh[((size_t)bh * L_CTX + m0 + ml) * HEAD_DIM + nl] = v;
            }
        }
    }
}

// ---------------------------------------------------------------------------
// Flash attention (R12 shape: 128 threads, warp owns 32 rows), tile load is
// now a pure cp.async copy of pre-formatted K/V fragments.
// ---------------------------------------------------------------------------
#define AT_THREADS 128
#define WOFF_QH  0
#define WOFF_QL  4096
#define WOFF_KH  8192
#define WOFF_KL  10272
#define WOFF_VF  12352
#define WOFF_P   17472
#define WOFF_MSK 21824
#define AT_SMEM_BYTES ((WOFF_MSK + 512) * 4)

__global__ void __launch_bounds__(128, 2)
attn_kernel(const int* __restrict__ mask) {
    extern __shared__ float smf[];
    uint32_t* QH = (uint32_t*)smf + WOFF_QH;
    uint32_t* QL = (uint32_t*)smf + WOFF_QL;
    uint32_t* KH = (uint32_t*)smf + WOFF_KH;
    uint32_t* KL = (uint32_t*)smf + WOFF_KL;
    float* Vf = smf + WOFF_VF;
    float* Pw = smf + WOFF_P;
    int*   msk = (int*)(smf + WOFF_MSK);
    const uint32_t smb = (uint32_t)__cvta_generic_to_shared(smf);

    const int bh = blockIdx.y;
    const int b = bh >> 4, h = bh & 15;
    const int q0 = blockIdx.x * 128;
    const int tid = threadIdx.x;
    const int lane = tid & 31, warp = tid >> 5;
    const int gid = lane >> 2, tig = lane & 3;

    for (int i = tid; i < L_CTX; i += AT_THREADS)
        msk[i] = mask[(size_t)b * TK + h + STRIDE * i];

    // ---- Q tile -> bf16 hi/lo fragment smem (built once) ----
    const float* Qb = g_Qh + ((size_t)bh * TQ + q0) * HEAD_DIM;
#pragma unroll
    for (int i = 0; i < 16; i++) {
        int idx = tid + i * AT_THREADS;
        int row = idx >> 4;
        int dc = (idx & 15) * 4;
        float4 v = *(const float4*)(Qb + row * 64 + dc);
        int mg = row >> 4;
        int rl = row & 15;
        int rowhalf = rl >> 3, gidr = rl & 7;
        int ks = dc >> 4;
        int khalf = ((dc & 15) >= 8) ? 1 : 0;
        int tigw = (dc & 7) >> 1;
        int j = (khalf << 1) | rowhalf;
        uint32_t h0 = pack_bf16x2(v.x, v.y);
        uint32_t h1 = pack_bf16x2(v.z, v.w);
        float h0a = __uint_as_float(h0 << 16);
        float h0b = __uint_as_float(h0 & 0xffff0000u);
        float h1a = __uint_as_float(h1 << 16);
        float h1b = __uint_as_float(h1 & 0xffff0000u);
        uint32_t l0 = pack_bf16x2(v.x - h0a, v.y - h0b);
        uint32_t l1 = pack_bf16x2(v.z - h1a, v.w - h1b);
        int base = ((ks * 8 + mg) * 32 + gidr * 4);
        QH[(base + tigw) * 4 + j] = h0;
        QH[(base + tigw + 1) * 4 + j] = h1;
        QL[(base + tigw) * 4 + j] = l0;
        QL[(base + tigw + 1) * 4 + j] = l1;
    }

    float* Pp = Pw + warp * (16 * 68);

    float oacc[2][8][4] = {};
    float M[2][2] = {{-1e30f, -1e30f}, {-1e30f, -1e30f}};
    float Ls[2][2] = {{0.f, 0.f}, {0.f, 0.f}};

#pragma unroll 1
    for (int lt = 0; lt < 8; lt++) {
        __syncthreads();
        // ---- cp.async copy of pre-formatted tile (2320 x 16B) ----
        {
            const char* khg = (const char*)(g_KHg + (size_t)(bh * 8 + lt) * 2080);
            const char* klg = (const char*)(g_KLg + (size_t)(bh * 8 + lt) * 2080);
            const char* vfg = (const char*)(g_VFg + (size_t)(bh * 8 + lt) * 5120);
            const uint32_t khd = smb + WOFF_KH * 4;
            const uint32_t kld = smb + WOFF_KL * 4;
            const uint32_t vfd = smb + WOFF_VF * 4;
#pragma unroll 2
            for (int i = tid; i < 2320; i += AT_THREADS) {
                if (i < 520)       cp_async16(khd + i * 16, khg + i * 16);
                else if (i < 1040) cp_async16(kld + (i - 520) * 16,
                                              klg + (size_t)(i - 520) * 16);
                else               cp_async16(vfd + (i - 1040) * 16,
                                              vfg + (size_t)(i - 1040) * 16);
            }
            cp_commit();
            cp_wait0();
        }
        __syncthreads();

        // ---- S = Q K^T : bf16 k16, 3-term split ----
        float sacc[2][8][4] = {};
#pragma unroll
        for (int ks = 0; ks < 4; ks++) {
            uint4 qh[2], ql[2];
#pragma unroll
            for (int mi = 0; mi < 2; mi++) {
                int qb = ((ks * 8 + (warp * 2 + mi)) * 32 + lane) * 4;
                qh[mi] = *(const uint4*)&QH[qb];
                ql[mi] = *(const uint4*)&QL[qb];
            }
#pragma unroll
            for (int ni = 0; ni < 8; ni++) {
                int n = ni * 8 + gid;
                int kb = ks * 520 + n * 8 + tig * 2;
                uint2 bh2 = *(const uint2*)&KH[kb];
                uint2 bl2 = *(const uint2*)&KL[kb];
#pragma unroll
                for (int mi = 0; mi < 2; mi++) {
                    mma_bf16(sacc[mi][ni], (const uint32_t*)&qh[mi], bh2.x, bh2.y);
                    mma_bf16(sacc[mi][ni], (const uint32_t*)&qh[mi], bl2.x, bl2.y);
                    mma_bf16(sacc[mi][ni], (const uint32_t*)&ql[mi], bh2.x, bh2.y);
                }
            }
        }

#pragma unroll
        for (int mi = 0; mi < 2; mi++) {
            float mt0 = -1e30f, mt1 = -1e30f;
#pragma unroll
            for (int ni = 0; ni < 8; ni++) {
                int c = lt * 64 + ni * 8 + 2 * tig;
                bool z0 = (msk[c] == 0), z1 = (msk[c + 1] == 0);
                sacc[mi][ni][0] = z0 ? -1e9f : sacc[mi][ni][0] * 0.125f;
                sacc[mi][ni][1] = z1 ? -1e9f : sacc[mi][ni][1] * 0.125f;
                sacc[mi][ni][2] = z0 ? -1e9f : sacc[mi][ni][2] * 0.125f;
                sacc[mi][ni][3] = z1 ? -1e9f : sacc[mi][ni][3] * 0.125f;
                mt0 = fmaxf(mt0, fmaxf(sacc[mi][ni][0], sacc[mi][ni][1]));
                mt1 = fmaxf(mt1, fmaxf(sacc[mi][ni][2], sacc[mi][ni][3]));
            }
            mt0 = fmaxf(mt0, __shfl_xor_sync(0xffffffffu, mt0, 1));
            mt0 = fmaxf(mt0, __shfl_xor_sync(0xffffffffu, mt0, 2));
            mt1 = fmaxf(mt1, __shfl_xor_sync(0xffffffffu, mt1, 1));
            mt1 = fmaxf(mt1, __shfl_xor_sync(0xffffffffu, mt1, 2));

            float Mn0 = fmaxf(M[mi][0], mt0), Mn1 = fmaxf(M[mi][1], mt1);
            float f0 = __expf(M[mi][0] - Mn0), f1 = __expf(M[mi][1] - Mn1);
            float s0 = 0.f, s1 = 0.f;
#pragma unroll
            for (int ni = 0; ni < 8; ni++) {
                int cc = ni * 8 + 2 * tig;
                float p00 = __expf(sacc[mi][ni][0] - Mn0);
                float p01 = __expf(sacc[mi][ni][1] - Mn0);
                float p10 = __expf(sacc[mi][ni][2] - Mn1);
                float p11 = __expf(sacc[mi][ni][3] - Mn1);
                s0 += p00 + p01; s1 += p10 + p11;
                Pp[gid * 68 + cc]           = tf32_round(p00);
                Pp[gid * 68 + cc + 1]       = tf32_round(p01);
                Pp[(gid + 8) * 68 + cc]     = tf32_round(p10);
                Pp[(gid + 8) * 68 + cc + 1] = tf32_round(p11);
            }
            s0 += __shfl_xor_sync(0xffffffffu, s0, 1);
            s0 += __shfl_xor_sync(0xffffffffu, s0, 2);
            s1 += __shfl_xor_sync(0xffffffffu, s1, 1);
            s1 += __shfl_xor_sync(0xffffffffu, s1, 2);
            Ls[mi][0] = Ls[mi][0] * f0 + s0;
            Ls[mi][1] = Ls[mi][1] * f1 + s1;
            M[mi][0] = Mn0; M[mi][1] = Mn1;
#pragma unroll
            for (int ni = 0; ni < 8; ni++) {
                oacc[mi][ni][0] *= f0; oacc[mi][ni][1] *= f0;
                oacc[mi][ni][2] *= f1; oacc[mi][ni][3] *= f1;
            }
            __syncwarp();

#pragma unroll
            for (int ks = 0; ks < 8; ks++) {
                uint32_t a[4];
                a[0] = __float_as_uint(Pp[gid * 68 + ks * 8 + tig]);
                a[1] = __float_as_uint(Pp[(gid + 8) * 68 + ks * 8 + tig]);
                a[2] = __float_as_uint(Pp[gid * 68 + ks * 8 + tig + 4]);
                a[3] = __float_as_uint(Pp[(gid + 8) * 68 + ks * 8 + tig + 4]);
#pragma unroll
                for (int ni = 0; ni < 8; ni++) {
                    int n = ni * 8 + gid;
                    int ip = ((ks * 64 + n) * 5 + ((tig + ks) & 3)) * 2;
                    float2 bv = *(const float2*)&Vf[ip];
                    mma_tf32(oacc[mi][ni], a,
                             __float_as_uint(bv.x), __float_as_uint(bv.y));
                }
            }
            __syncwarp();
        }
    }

#pragma unroll
    for (int mi = 0; mi < 2; mi++) {
        float inv0 = 1.0f / Ls[mi][0], inv1 = 1.0f / Ls[mi][1];
        int r0 = q0 + warp * 32 + mi * 16 + gid;
#pragma unroll
        for (int ni = 0; ni < 8; ni++) {
            int col = h * 64 + ni * 8 + 2 * tig;
            size_t base0 = ((size_t)b * TQ + r0) * D_MODEL + col;
            *(float2*)&g_ctx[base0] =
                make_float2(tf32_round(oacc[mi][ni][0] * inv0),
                            tf32_round(oacc[mi][ni][1] * inv0));
            *(float2*)&g_ctx[base0 + (size_t)8 * D_MODEL] =
                make_float2(tf32_round(oacc[mi][ni][2] * inv1),
                            tf32_round(oacc[mi][ni][3] * inv1));
        }
    }
}

// ---------------------------------------------------------------------------
extern "C" void kernel_launch(void* const* d_in, const int* in_sizes, int n_in,
                              void* d_out, int out_size) {
    const float* q        = (const float*)d_in[0];
    const float* k        = (const float*)d_in[1];
    const float* v        = (const float*)d_in[2];
    const int*   src_mask = (const int*)d_in[3];
    const float* w_q      = (const float*)d_in[4];
    const float* b_q      = (const float*)d_in[5];
    const float* w_k      = (const float*)d_in[6];
    const float* b_k      = (const float*)d_in[7];
    const float* w_v      = (const float*)d_in[8];
    const float* b_v      = (const float*)d_in[9];
    const float* w_o      = (const float*)d_in[10];
    const float* b_o      = (const float*)d_in[11];
    float* out = (float*)d_out;

    constexpr int ASM = 3 * (128 * 36 + 128 * 36) * 4;       // 110592
    constexpr int PSM_64 = 2 * (128 * 36 + 64 * 36) * 4;     // 55296

    cudaFuncSetAttribute(attn_kernel,
                         cudaFuncAttributeMaxDynamicSharedMemorySize,
                         AT_SMEM_BYTES);
    cudaFuncSetAttribute(async_gemm_kernel<0>,
                         cudaFuncAttributeMaxDynamicSharedMemorySize, ASM);
    cudaFuncSetAttribute(async_gemm_kernel<3>,
                         cudaFuncAttributeMaxDynamicSharedMemorySize, ASM);
    cudaFuncSetAttribute(tf32_gemm_kernel<64, 1>,
                         cudaFuncAttributeMaxDynamicSharedMemorySize, PSM_64);
    cudaFuncSetAttribute(tf32_gemm_kernel<64, 2>,
                         cudaFuncAttributeMaxDynamicSharedMemorySize, PSM_64);

    float* d_qr = nullptr;  cudaGetSymbolAddress((void**)&d_qr, g_qr);
    float* d_rw = nullptr;  cudaGetSymbolAddress((void**)&d_rw, g_rw);
    round4_kernel<<<(B_SZ * TQ * D_MODEL) / 1024, 256>>>(q, d_qr);
    round4_kernel<<<(D_MODEL * D_MODEL) / 1024, 256>>>(w_q, d_rw);
    round4_kernel<<<(D_MODEL * D_MODEL) / 1024, 256>>>(
        w_o, d_rw + (size_t)D_MODEL * D_MODEL);

    async_gemm_kernel<0><<<dim3(8, 64), 256, ASM>>>(b_q, nullptr);
    tf32_gemm_kernel<64, 1><<<dim3(L_CTX / 128, B_SZ * N_HEAD), 256,
                              PSM_64>>>(k, w_k, b_k);
    tf32_gemm_kernel<64, 2><<<dim3(L_CTX / 128, B_SZ * N_HEAD), 256,
                              PSM_64>>>(v, w_v, b_v);

    // one-time K/V fragment formatting
    fmt_kv_kernel<<<dim3(8, B_SZ * N_HEAD), 128>>>();

    attn_kernel<<<dim3(TQ / 128, B_SZ * N_HEAD), 128, AT_SMEM_BYTES>>>(src_mask);

    async_gemm_kernel<3><<<dim3(8, 64), 256, ASM>>>(b_o, out);
}

// round 16
// speedup vs baseline: 1.0176x; 1.0146x over previous
#include <cuda_runtime.h>
#include <cstdint>

#define D_MODEL 1024
#define N_HEAD 16
#define HEAD_DIM 64
#define B_SZ 4
#define TQ 2048
#define TK 8192
#define STRIDE 16
#define L_CTX 512

__device__ float g_Qh[(size_t)B_SZ * N_HEAD * TQ * HEAD_DIM];
__device__ float g_Kh[(size_t)B_SZ * N_HEAD * L_CTX * HEAD_DIM];
__device__ float g_Vh[(size_t)B_SZ * N_HEAD * L_CTX * HEAD_DIM];
__device__ float g_ctx[(size_t)B_SZ * TQ * D_MODEL];
__device__ float g_qr[(size_t)B_SZ * TQ * D_MODEL];
__device__ float g_rw[(size_t)2 * D_MODEL * D_MODEL];
// pre-formatted K/V fragment buffers: per (bh, lt) segment
__device__ __align__(16) uint32_t g_KHg[(size_t)64 * 8 * 2080];
__device__ __align__(16) uint32_t g_KLg[(size_t)64 * 8 * 2080];
__device__ __align__(16) float    g_VFg[(size_t)64 * 8 * 5120];

// ---------------------------------------------------------------------------
__device__ __forceinline__ float tf32_round(float x) {
    uint32_t u;
    asm("cvt.rna.tf32.f32 %0, %1;" : "=r"(u) : "f"(x));
    return __uint_as_float(u);
}
__device__ __forceinline__ uint32_t pack_bf16x2(float lo, float hi) {
    uint32_t r;
    asm("cvt.rn.bf16x2.f32 %0, %1, %2;" : "=r"(r) : "f"(hi), "f"(lo));
    return r;
}
__device__ __forceinline__ void mma_tf32(float* c, const uint32_t* a,
                                         uint32_t b0, uint32_t b1) {
    asm volatile(
        "mma.sync.aligned.m16n8k8.row.col.f32.tf32.tf32.f32 "
        "{%0,%1,%2,%3}, {%4,%5,%6,%7}, {%8,%9}, {%0,%1,%2,%3};\n"
        : "+f"(c[0]), "+f"(c[1]), "+f"(c[2]), "+f"(c[3])
        : "r"(a[0]), "r"(a[1]), "r"(a[2]), "r"(a[3]), "r"(b0), "r"(b1));
}
__device__ __forceinline__ void mma_bf16(float* c, const uint32_t* a,
                                         uint32_t b0, uint32_t b1) {
    asm volatile(
        "mma.sync.aligned.m16n8k16.row.col.f32.bf16.bf16.f32 "
        "{%0,%1,%2,%3}, {%4,%5,%6,%7}, {%8,%9}, {%0,%1,%2,%3};\n"
        : "+f"(c[0]), "+f"(c[1]), "+f"(c[2]), "+f"(c[3])
        : "r"(a[0]), "r"(a[1]), "r"(a[2]), "r"(a[3]), "r"(b0), "r"(b1));
}
__device__ __forceinline__ void ldsm_x4(uint32_t* r, uint32_t saddr) {
    asm volatile(
        "ldmatrix.sync.aligned.m8n8.x4.shared.b16 {%0,%1,%2,%3}, [%4];"
        : "=r"(r[0]), "=r"(r[1]), "=r"(r[2]), "=r"(r[3]) : "r"(saddr));
}
__device__ __forceinline__ void cp_async16(uint32_t saddr, const void* gptr) {
    asm volatile("cp.async.cg.shared.global [%0], [%1], 16;\n"
                 :: "r"(saddr), "l"(gptr));
}
__device__ __forceinline__ void cp_commit() {
    asm volatile("cp.async.commit_group;\n");
}
__device__ __forceinline__ void cp_wait1() {
    asm volatile("cp.async.wait_group 1;\n" ::: "memory");
}
__device__ __forceinline__ void cp_wait0() {
    asm volatile("cp.async.wait_group 0;\n" ::: "memory");
}

// ---------------------------------------------------------------------------
__global__ void round4_kernel(const float* __restrict__ src,
                              float* __restrict__ dst) {
    size_t i = ((size_t)blockIdx.x * 256 + threadIdx.x) * 4;
    float4 v = *(const float4*)(src + i);
    *(float4*)(dst + i) = make_float4(tf32_round(v.x), tf32_round(v.y),
                                      tf32_round(v.z), tf32_round(v.w));
}

// ---------------------------------------------------------------------------
// Format K/V tiles once into fragment-ready global buffers. (R14)
// ---------------------------------------------------------------------------
__global__ void __launch_bounds__(128)
fmt_kv_kernel() {
    const int lt = blockIdx.x, bh = blockIdx.y;
    const int tid = threadIdx.x;
    const float* Kb = g_Kh + (size_t)bh * L_CTX * HEAD_DIM;
    const float* Vb = g_Vh + (size_t)bh * L_CTX * HEAD_DIM;
    uint32_t* KH = g_KHg + (size_t)(bh * 8 + lt) * 2080;
    uint32_t* KL = g_KLg + (size_t)(bh * 8 + lt) * 2080;
    float*    VF = g_VFg + (size_t)(bh * 8 + lt) * 5120;

#pragma unroll
    for (int i = 0; i < 8; i++) {
        int idx = tid + i * 128;
        int r = idx >> 4;
        int dc = (idx & 15) * 4;
        float4 kv = *(const float4*)(Kb + (size_t)(lt * 64 + r) * 64 + dc);
        int ks = dc >> 4;
        int khalf = ((dc & 15) >= 8) ? 1 : 0;
        int tigw = (dc & 7) >> 1;
        uint32_t h0 = pack_bf16x2(kv.x, kv.y);
        uint32_t h1 = pack_bf16x2(kv.z, kv.w);
        float h0a = __uint_as_float(h0 << 16);
        float h0b = __uint_as_float(h0 & 0xffff0000u);
        float h1a = __uint_as_float(h1 << 16);
        float h1b = __uint_as_float(h1 & 0xffff0000u);
        uint32_t l0 = pack_bf16x2(kv.x - h0a, kv.y - h0b);
        uint32_t l1 = pack_bf16x2(kv.z - h1a, kv.w - h1b);
        int kb = ks * 520 + r * 8 + khalf;
        KH[kb + tigw * 2] = h0;
        KH[kb + (tigw + 1) * 2] = h1;
        KL[kb + tigw * 2] = l0;
        KL[kb + (tigw + 1) * 2] = l1;

        float4 vv = *(const float4*)(Vb + (size_t)(lt * 64 + r) * 64 + dc);
        float vl[4] = {vv.x, vv.y, vv.z, vv.w};
        int vks = r >> 3, vkh = (r >> 2) & 1;
        int vte = ((r & 3) + vks) & 3;
#pragma unroll
        for (int e = 0; e < 4; e++)
            VF[((vks * 64 + (dc + e)) * 5 + vte) * 2 + vkh] = tf32_round(vl[e]);
    }
}

// ---------------------------------------------------------------------------
// Pure cp.async tf32 GEMM (pre-rounded operands), LDSM fragment loads. (R12)
// MODE 0: Q proj, 3: O proj.
// ---------------------------------------------------------------------------
template <int MODE>
__global__ void __launch_bounds__(256, 2)
async_gemm_kernel(const float* __restrict__ bias, float* __restrict__ Cout) {
    extern __shared__ float dsm[];
    constexpr int KS = 36;
    constexpr int STG = 128 * KS;
    constexpr int NKI = D_MODEL / 32;
    const uint32_t smem_u32 = (uint32_t)__cvta_generic_to_shared(dsm);

    const int tid = threadIdx.x;
    const int lane = tid & 31, warp = tid >> 5;
    const int gid = lane >> 2, tig = lane & 3;

    const int m0 = blockIdx.y * 128;
    const int n_base = blockIdx.x * 128;
    const float* A = (MODE == 0) ? g_qr : g_ctx;
    const float* W = g_rw + (size_t)((MODE == 0) ? 0 : 1) * D_MODEL * D_MODEL;

    const int wm = (warp >> 1) * 32;
    const int wn = (warp & 1) * 64;

    float acc[2][8][4] = {};

    auto CP = [&](int step) {
        int st = step % 3;
#pragma unroll
        for (int i = 0; i < 4; i++) {
            int idx = tid + i * 256;
            int row = idx >> 3, kc = (idx & 7) * 4;
            cp_async16(smem_u32 + (uint32_t)(st * STG + row * KS + kc) * 4,
                       A + (size_t)(m0 + row) * D_MODEL + step * 32 + kc);
        }
#pragma unroll
        for (int i = 0; i < 4; i++) {
            int idx = tid + i * 256;
            int row = idx >> 3, kc = (idx & 7) * 4;
            cp_async16(smem_u32 + (uint32_t)(3 * STG + st * STG + row * KS + kc) * 4,
                       W + (size_t)(n_base + row) * D_MODEL + step * 32 + kc);
        }
        cp_commit();
    };

    const int l15 = lane & 15;
    const int akh = (lane >> 4) * 4;
    const uint32_t aOff = (uint32_t)(((wm + l15) * KS) + akh) * 4;
    const int wrow = wn + ((lane >> 4) << 3) + (lane & 7);
    const int wkh = ((lane >> 3) & 1) * 4;
    const uint32_t wOff = (uint32_t)((wrow * KS) + wkh) * 4;

    auto MMA = [&](int st) {
        uint32_t aB = smem_u32 + (uint32_t)(st * STG) * 4 + aOff;
        uint32_t wB = smem_u32 + (uint32_t)((3 + st) * STG) * 4 + wOff;
#pragma unroll
        for (int ks = 0; ks < 32; ks += 8) {
            uint32_t a0[4], a1[4];
            ldsm_x4(a0, aB + ks * 4);
            ldsm_x4(a1, aB + 16 * KS * 4 + ks * 4);
#pragma unroll
            for (int p = 0; p < 4; p++) {
                uint32_t w[4];
                ldsm_x4(w, wB + (uint32_t)(p * 16 * KS + ks) * 4);
                mma_tf32(acc[0][2 * p],     a0, w[0], w[1]);
                mma_tf32(acc[1][2 * p],     a1, w[0], w[1]);
                mma_tf32(acc[0][2 * p + 1], a0, w[2], w[3]);
                mma_tf32(acc[1][2 * p + 1], a1, w[2], w[3]);
            }
        }
    };

    CP(0);
    CP(1);
    cp_wait1();
    __syncthreads();
#pragma unroll 1
    for (int c = 0; c < NKI; c++) {
        if (c + 2 < NKI) CP(c + 2);
        MMA(c % 3);
        if (c + 2 < NKI) cp_wait1(); else cp_wait0();
        __syncthreads();
    }

#pragma unroll
    for (int mi = 0; mi < 2; mi++) {
#pragma unroll
        for (int ni = 0; ni < 8; ni++) {
#pragma unroll
            for (int r = 0; r < 4; r++) {
                int ml = wm + mi * 16 + gid + ((r >> 1) ? 8 : 0);
                int nl = wn + ni * 8 + 2 * tig + (r & 1);
                float v = acc[mi][ni][r];
                if (MODE == 0) {
                    int m = m0 + ml;
                    int n = n_base + nl;
                    int bb = m >> 11, tq = m & 2047;
                    int hh = n >> 6, d = n & 63;
                    g_Qh[(((size_t)bb * N_HEAD + hh) * TQ + tq) * HEAD_DIM + d] =
                        v + bias[n];
                } else {
                    Cout[(size_t)(m0 + ml) * D_MODEL + n_base + nl] =
                        v + bias[n_base + nl];
                }
            }
        }
    }
}

// ---------------------------------------------------------------------------
// R12 tf32 GEMM for sliced K/V projections (LDSM). MODE 1: K, 2: V. BN=64.
// ---------------------------------------------------------------------------
template <int BN, int MODE>
__global__ void __launch_bounds__(256, 2)
tf32_gemm_kernel(const float* __restrict__ Ain,
                 const float* __restrict__ W,
                 const float* __restrict__ bias) {
    extern __shared__ float dsm[];
    constexpr int KS = 36;
    constexpr int ASTAGE = 128 * KS;
    constexpr int WSTAGE = BN * KS;
    float* Asb[2] = {dsm, dsm + ASTAGE + WSTAGE};
    float* Wsb[2] = {dsm + ASTAGE, dsm + 2 * ASTAGE + WSTAGE};
    const uint32_t smem_u32 = (uint32_t)__cvta_generic_to_shared(dsm);

    const int tid = threadIdx.x;
    const int lane = tid & 31, warp = tid >> 5;
    const int gid = lane >> 2, tig = lane & 3;

    const int bh = blockIdx.y;
    const int b = bh >> 4, h = bh & 15;
    const int m0 = blockIdx.x * 128;
    const float* A = Ain + (size_t)b * TK * D_MODEL;
    const int n_base = h * 64;

    const int wm = (warp >> 1) * 32;
    const int wn = (warp & 1) * (BN / 2);
    constexpr int NF = BN / 16;
    constexpr int WL = BN / 32;

    float acc[2][NF][4] = {};
    float4 avS[4];
    float4 wvS[WL];

    auto LOAD = [&](int k0) {
#pragma unroll
        for (int i = 0; i < 4; i++) {
            int idx = tid + i * 256;
            int row = idx >> 3, kc = (idx & 7) * 4;
            int grow = h + STRIDE * (m0 + row);
            avS[i] = *(const float4*)(A + (size_t)grow * D_MODEL + k0 + kc);
        }
#pragma unroll
        for (int i = 0; i < WL; i++) {
            int idx = tid + i * 256;
            int nrow = idx >> 3, kc = (idx & 7) * 4;
            wvS[i] = *(const float4*)(W + (size_t)(n_base + nrow) * D_MODEL + k0 + kc);
        }
    };
    auto STORE = [&](int s) {
        float* As = Asb[s];
        float* Ws = Wsb[s];
#pragma unroll
        for (int i = 0; i < 4; i++) {
            int idx = tid + i * 256;
            int row = idx >> 3, kc = (idx & 7) * 4;
            float4 r = make_float4(tf32_round(avS[i].x), tf32_round(avS[i].y),
                                   tf32_round(avS[i].z), tf32_round(avS[i].w));
            *(float4*)&As[row * KS + kc] = r;
        }
#pragma unroll
        for (int i = 0; i < WL; i++) {
            int idx = tid + i * 256;
            int nrow = idx >> 3, kc = (idx & 7) * 4;
            float4 r = make_float4(tf32_round(wvS[i].x), tf32_round(wvS[i].y),
                                   tf32_round(wvS[i].z), tf32_round(wvS[i].w));
            *(float4*)&Ws[nrow * KS + kc] = r;
        }
    };

    const int l15 = lane & 15;
    const int akh = (lane >> 4) * 4;
    const uint32_t aOff = (uint32_t)(((wm + l15) * KS) + akh) * 4;
    const int wrow = wn + ((lane >> 4) << 3) + (lane & 7);
    const int wkh = ((lane >> 3) & 1) * 4;
    const uint32_t wOff = (uint32_t)((wrow * KS) + wkh) * 4;

    auto MMA = [&](int s) {
        uint32_t aB = smem_u32 + (uint32_t)(s * (ASTAGE + WSTAGE)) * 4 + aOff;
        uint32_t wB = smem_u32 +
                      (uint32_t)(ASTAGE + s * (ASTAGE + WSTAGE)) * 4 + wOff;
#pragma unroll
        for (int ks = 0; ks < 32; ks += 8) {
            uint32_t a0[4], a1[4];
            ldsm_x4(a0, aB + ks * 4);
            ldsm_x4(a1, aB + 16 * KS * 4 + ks * 4);
#pragma unroll
            for (int p = 0; p < NF / 2; p++) {
                uint32_t w[4];
                ldsm_x4(w, wB + (uint32_t)(p * 16 * KS + ks) * 4);
                mma_tf32(acc[0][2 * p],     a0, w[0], w[1]);
                mma_tf32(acc[1][2 * p],     a1, w[0], w[1]);
                mma_tf32(acc[0][2 * p + 1], a0, w[2], w[3]);
                mma_tf32(acc[1][2 * p + 1], a1, w[2], w[3]);
            }
        }
    };

    LOAD(0);
    STORE(0);
    __syncthreads();
    int s = 0;
#pragma unroll 1
    for (int k0 = 32; k0 < D_MODEL; k0 += 32) {
        LOAD(k0);
        MMA(s);
        STORE(s ^ 1);
        __syncthreads();
        s ^= 1;
    }
    MMA(s);

#pragma unroll
    for (int mi = 0; mi < 2; mi++) {
#pragma unroll
        for (int ni = 0; ni < NF; ni++) {
#pragma unroll
            for (int r = 0; r < 4; r++) {
                int ml = wm + mi * 16 + gid + ((r >> 1) ? 8 : 0);
                int nl = wn + ni * 8 + 2 * tig + (r & 1);
                float v = acc[mi][ni][r] + bias[n_base + nl];
                if (MODE == 1)
                    g_Kh[((size_t)bh * L_CTX + m0 + ml) * HEAD_DIM + nl] = v;
                else
                    g_Vh[((size_t)bh * L_CTX + m0 + ml) * HEAD_DIM + nl] = v;
            }
        }
    }
}

// ---------------------------------------------------------------------------
// Flash attention: 128 threads, warp owns 32 rows. Double-buffered K stages;
// V single-stage, loaded overlapping the next tile's S-phase.
// smem words: QH 0(4096) QL 4096(4096) K0 8192(4160) K1 12352(4160)
//             VF 16512(5120) P 21632(4352) MSK 25984(512)  => 105984 B
// ---------------------------------------------------------------------------
#define AT_THREADS 128
#define WOFF_QH  0
#define WOFF_QL  4096
#define WOFF_K0  8192
#define WOFF_K1  12352
#define WOFF_VF  16512
#define WOFF_P   21632
#define WOFF_MSK 25984
#define AT_SMEM_BYTES ((WOFF_MSK + 512) * 4)

__global__ void __launch_bounds__(128, 2)
attn_kernel(const int* __restrict__ mask) {
    extern __shared__ float smf[];
    uint32_t* QH = (uint32_t*)smf + WOFF_QH;
    uint32_t* QL = (uint32_t*)smf + WOFF_QL;
    float* Vf = smf + WOFF_VF;
    float* Pw = smf + WOFF_P;
    int*   msk = (int*)(smf + WOFF_MSK);
    const uint32_t smb = (uint32_t)__cvta_generic_to_shared(smf);

    const int bh = blockIdx.y;
    const int b = bh >> 4, h = bh & 15;
    const int q0 = blockIdx.x * 128;
    const int tid = threadIdx.x;
    const int lane = tid & 31, warp = tid >> 5;
    const int gid = lane >> 2, tig = lane & 3;

    // async copy helpers over pre-formatted fragments
    const char* KHg0 = (const char*)(g_KHg + (size_t)bh * 8 * 2080);
    const char* KLg0 = (const char*)(g_KLg + (size_t)bh * 8 * 2080);
    const char* VFg0 = (const char*)(g_VFg + (size_t)bh * 8 * 5120);
    auto COPYK = [&](int lt, int st) {
        const char* khg = KHg0 + (size_t)lt * 2080 * 4;
        const char* klg = KLg0 + (size_t)lt * 2080 * 4;
        uint32_t kd = smb + (WOFF_K0 + st * 4160) * 4;
        uint32_t ld = kd + 2080 * 4;
        for (int i = tid; i < 1040; i += AT_THREADS) {
            if (i < 520) cp_async16(kd + i * 16, khg + (size_t)i * 16);
            else         cp_async16(ld + (i - 520) * 16,
                                    klg + (size_t)(i - 520) * 16);
        }
        cp_commit();
    };
    auto COPYV = [&](int lt) {
        const char* vfg = VFg0 + (size_t)lt * 5120 * 4;
        uint32_t vd = smb + WOFF_VF * 4;
        for (int i = tid; i < 1280; i += AT_THREADS)
            cp_async16(vd + i * 16, vfg + (size_t)i * 16);
        cp_commit();
    };

    // kick off first tile's loads immediately
    COPYK(0, 0);
    COPYV(0);

    for (int i = tid; i < L_CTX; i += AT_THREADS)
        msk[i] = mask[(size_t)b * TK + h + STRIDE * i];

    // ---- Q tile -> bf16 hi/lo fragment smem (built once) ----
    const float* Qb = g_Qh + ((size_t)bh * TQ + q0) * HEAD_DIM;
#pragma unroll
    for (int i = 0; i < 16; i++) {
        int idx = tid + i * AT_THREADS;
        int row = idx >> 4;
        int dc = (idx & 15) * 4;
        float4 v = *(const float4*)(Qb + row * 64 + dc);
        int mg = row >> 4;
        int rl = row & 15;
        int rowhalf = rl >> 3, gidr = rl & 7;
        int ks = dc >> 4;
        int khalf = ((dc & 15) >= 8) ? 1 : 0;
        int tigw = (dc & 7) >> 1;
        int j = (khalf << 1) | rowhalf;
        uint32_t h0 = pack_bf16x2(v.x, v.y);
        uint32_t h1 = pack_bf16x2(v.z, v.w);
        float h0a = __uint_as_float(h0 << 16);
        float h0b = __uint_as_float(h0 & 0xffff0000u);
        float h1a = __uint_as_float(h1 << 16);
        float h1b = __uint_as_float(h1 & 0xffff0000u);
        uint32_t l0 = pack_bf16x2(v.x - h0a, v.y - h0b);
        uint32_t l1 = pack_bf16x2(v.z - h1a, v.w - h1b);
        int base = ((ks * 8 + mg) * 32 + gidr * 4);
        QH[(base + tigw) * 4 + j] = h0;
        QH[(base + tigw + 1) * 4 + j] = h1;
        QL[(base + tigw) * 4 + j] = l0;
        QL[(base + tigw + 1) * 4 + j] = l1;
    }

    float* Pp = Pw + warp * (16 * 68);

    float oacc[2][8][4] = {};
    float M[2][2] = {{-1e30f, -1e30f}, {-1e30f, -1e30f}};
    float Ls[2][2] = {{0.f, 0.f}, {0.f, 0.f}};

    int cur = 0;
#pragma unroll 1
    for (int lt = 0; lt < 8; lt++) {
        // K(lt) ready (outstanding: [K(lt), V(lt)] or [K(lt), V(lt)] tail)
        cp_wait1();
        __syncthreads();

        uint32_t* KH = (uint32_t*)smf + (WOFF_K0 + cur * 4160);
        uint32_t* KL = KH + 2080;

        // ---- S = Q K^T : bf16 k16, 3-term split ----
        float sacc[2][8][4] = {};
#pragma unroll
        for (int ks = 0; ks < 4; ks++) {
            uint4 qh[2], ql[2];
#pragma unroll
            for (int mi = 0; mi < 2; mi++) {
                int qb = ((ks * 8 + (warp * 2 + mi)) * 32 + lane) * 4;
                qh[mi] = *(const uint4*)&QH[qb];
                ql[mi] = *(const uint4*)&QL[qb];
            }
#pragma unroll
            for (int ni = 0; ni < 8; ni++) {
                int n = ni * 8 + gid;
                int kb = ks * 520 + n * 8 + tig * 2;
                uint2 bh2 = *(const uint2*)&KH[kb];
                uint2 bl2 = *(const uint2*)&KL[kb];
#pragma unroll
                for (int mi = 0; mi < 2; mi++) {
                    mma_bf16(sacc[mi][ni], (const uint32_t*)&qh[mi], bh2.x, bh2.y);
                    mma_bf16(sacc[mi][ni], (const uint32_t*)&qh[mi], bl2.x, bl2.y);
                    mma_bf16(sacc[mi][ni], (const uint32_t*)&ql[mi], bh2.x, bh2.y);
                }
            }
        }

        // prefetch next K into the other stage (overlaps softmax + PV)
        if (lt < 7) {
            COPYK(lt + 1, cur ^ 1);
            cp_wait1();          // V(lt) done; K(lt+1) in flight
        } else {
            cp_wait0();          // V(7) done
        }
        __syncthreads();

        // ---- per m-half: mask + online softmax + P + PV ----
#pragma unroll
        for (int mi = 0; mi < 2; mi++) {
            float mt0 = -1e30f, mt1 = -1e30f;
#pragma unroll
            for (int ni = 0; ni < 8; ni++) {
                int c = lt * 64 + ni * 8 + 2 * tig;
                bool z0 = (msk[c] == 0), z1 = (msk[c + 1] == 0);
                sacc[mi][ni][0] = z0 ? -1e9f : sacc[mi][ni][0] * 0.125f;
                sacc[mi][ni][1] = z1 ? -1e9f : sacc[mi][ni][1] * 0.125f;
                sacc[mi][ni][2] = z0 ? -1e9f : sacc[mi][ni][2] * 0.125f;
                sacc[mi][ni][3] = z1 ? -1e9f : sacc[mi][ni][3] * 0.125f;
                mt0 = fmaxf(mt0, fmaxf(sacc[mi][ni][0], sacc[mi][ni][1]));
                mt1 = fmaxf(mt1, fmaxf(sacc[mi][ni][2], sacc[mi][ni][3]));
            }
            mt0 = fmaxf(mt0, __shfl_xor_sync(0xffffffffu, mt0, 1));
            mt0 = fmaxf(mt0, __shfl_xor_sync(0xffffffffu, mt0, 2));
            mt1 = fmaxf(mt1, __shfl_xor_sync(0xffffffffu, mt1, 1));
            mt1 = fmaxf(mt1, __shfl_xor_sync(0xffffffffu, mt1, 2));

            float Mn0 = fmaxf(M[mi][0], mt0), Mn1 = fmaxf(M[mi][1], mt1);
            float f0 = __expf(M[mi][0] - Mn0), f1 = __expf(M[mi][1] - Mn1);
            float s0 = 0.f, s1 = 0.f;
#pragma unroll
            for (int ni = 0; ni < 8; ni++) {
                int cc = ni * 8 + 2 * tig;
                float p00 = __expf(sacc[mi][ni][0] - Mn0);
                float p01 = __expf(sacc[mi][ni][1] - Mn0);
                float p10 = __expf(sacc[mi][ni][2] - Mn1);
                float p11 = __expf(sacc[mi][ni][3] - Mn1);
                s0 += p00 + p01; s1 += p10 + p11;
                Pp[gid * 68 + cc]           = tf32_round(p00);
                Pp[gid * 68 + cc + 1]       = tf32_round(p01);
                Pp[(gid + 8) * 68 + cc]     = tf32_round(p10);
                Pp[(gid + 8) * 68 + cc + 1] = tf32_round(p11);
            }
            s0 += __shfl_xor_sync(0xffffffffu, s0, 1);
            s0 += __shfl_xor_sync(0xffffffffu, s0, 2);
            s1 += __shfl_xor_sync(0xffffffffu, s1, 1);
            s1 += __shfl_xor_sync(0xffffffffu, s1, 2);
            Ls[mi][0] = Ls[mi][0] * f0 + s0;
            Ls[mi][1] = Ls[mi][1] * f1 + s1;
            M[mi][0] = Mn0; M[mi][1] = Mn1;
#pragma unroll
            for (int ni = 0; ni < 8; ni++) {
                oacc[mi][ni][0] *= f0; oacc[mi][ni][1] *= f0;
                oacc[mi][ni][2] *= f1; oacc[mi][ni][3] *= f1;
            }
            __syncwarp();

#pragma unroll
            for (int ks = 0; ks < 8; ks++) {
                uint32_t a[4];
                a[0] = __float_as_uint(Pp[gid * 68 + ks * 8 + tig]);
                a[1] = __float_as_uint(Pp[(gid + 8) * 68 + ks * 8 + tig]);
                a[2] = __float_as_uint(Pp[gid * 68 + ks * 8 + tig + 4]);
                a[3] = __float_as_uint(Pp[(gid + 8) * 68 + ks * 8 + tig + 4]);
#pragma unroll
                for (int ni = 0; ni < 8; ni++) {
                    int n = ni * 8 + gid;
                    int ip = ((ks * 64 + n) * 5 + ((tig + ks) & 3)) * 2;
                    float2 bv = *(const float2*)&Vf[ip];
                    mma_tf32(oacc[mi][ni], a,
                             __float_as_uint(bv.x), __float_as_uint(bv.y));
                }
            }
            __syncwarp();
        }

        // all warps done with Vf -> prefetch next V (overlaps next S-phase)
        __syncthreads();
        if (lt < 7) COPYV(lt + 1);
        cur ^= 1;
    }

#pragma unroll
    for (int mi = 0; mi < 2; mi++) {
        float inv0 = 1.0f / Ls[mi][0], inv1 = 1.0f / Ls[mi][1];
        int r0 = q0 + warp * 32 + mi * 16 + gid;
#pragma unroll
        for (int ni = 0; ni < 8; ni++) {
            int col = h * 64 + ni * 8 + 2 * tig;
            size_t base0 = ((size_t)b * TQ + r0) * D_MODEL + col;
            *(float2*)&g_ctx[base0] =
                make_float2(tf32_round(oacc[mi][ni][0] * inv0),
                            tf32_round(oacc[mi][ni][1] * inv0));
            *(float2*)&g_ctx[base0 + (size_t)8 * D_MODEL] =
                make_float2(tf32_round(oacc[mi][ni][2] * inv1),
                            tf32_round(oacc[mi][ni][3] * inv1));
        }
    }
}

// ---------------------------------------------------------------------------
extern "C" void kernel_launch(void* const* d_in, const int* in_sizes, int n_in,
                              void* d_out, int out_size) {
    const float* q        = (const float*)d_in[0];
    const float* k        = (const float*)d_in[1];
    const float* v        = (const float*)d_in[2];
    const int*   src_mask = (const int*)d_in[3];
    const float* w_q      = (const float*)d_in[4];
    const float* b_q      = (const float*)d_in[5];
    const float* w_k      = (const float*)d_in[6];
    const float* b_k      = (const float*)d_in[7];
    const float* w_v      = (const float*)d_in[8];
    const float* b_v      = (const float*)d_in[9];
    const float* w_o      = (const float*)d_in[10];
    const float* b_o      = (const float*)d_in[11];
    float* out = (float*)d_out;

    constexpr int ASM = 3 * (128 * 36 + 128 * 36) * 4;       // 110592
    constexpr int PSM_64 = 2 * (128 * 36 + 64 * 36) * 4;     // 55296

    cudaFuncSetAttribute(attn_kernel,
                         cudaFuncAttributeMaxDynamicSharedMemorySize,
                         AT_SMEM_BYTES);
    cudaFuncSetAttribute(async_gemm_kernel<0>,
                         cudaFuncAttributeMaxDynamicSharedMemorySize, ASM);
    cudaFuncSetAttribute(async_gemm_kernel<3>,
                         cudaFuncAttributeMaxDynamicSharedMemorySize, ASM);
    cudaFuncSetAttribute(tf32_gemm_kernel<64, 1>,
                         cudaFuncAttributeMaxDynamicSharedMemorySize, PSM_64);
    cudaFuncSetAttribute(tf32_gemm_kernel<64, 2>,
                         cudaFuncAttributeMaxDynamicSharedMemorySize, PSM_64);

    float* d_qr = nullptr;  cudaGetSymbolAddress((void**)&d_qr, g_qr);
    float* d_rw = nullptr;  cudaGetSymbolAddress((void**)&d_rw, g_rw);
    round4_kernel<<<(B_SZ * TQ * D_MODEL) / 1024, 256>>>(q, d_qr);
    round4_kernel<<<(D_MODEL * D_MODEL) / 1024, 256>>>(w_q, d_rw);
    round4_kernel<<<(D_MODEL * D_MODEL) / 1024, 256>>>(
        w_o, d_rw + (size_t)D_MODEL * D_MODEL);

    async_gemm_kernel<0><<<dim3(8, 64), 256, ASM>>>(b_q, nullptr);
    tf32_gemm_kernel<64, 1><<<dim3(L_CTX / 128, B_SZ * N_HEAD), 256,
                              PSM_64>>>(k, w_k, b_k);
    tf32_gemm_kernel<64, 2><<<dim3(L_CTX / 128, B_SZ * N_HEAD), 256,
                              PSM_64>>>(v, w_v, b_v);

    fmt_kv_kernel<<<dim3(8, B_SZ * N_HEAD), 128>>>();

    attn_kernel<<<dim3(TQ / 128, B_SZ * N_HEAD), 128, AT_SMEM_BYTES>>>(src_mask);

    async_gemm_kernel<3><<<dim3(8, 64), 256, ASM>>>(b_o, out);
}